// round 16
// baseline (speedup 1.0000x reference)
#include <cuda_runtime.h>

#define SEQ 4096
#define DM  1024
#define NH  16
#define D3  3072
#define LA  68     // attn smem row stride (floats)
#define LG  36     // gemm smem row stride (floats)

// tf32-rounded operands for the projection GEMM
__device__ float g_xr[SEQ * DM];    // x, rounded
__device__ float g_wt[D3 * DM];     // W^T [n][k], rounded
// fp32 scratch: kqv K|Q chunks (V chunk unused), tf32-rounded, Q pre-scaled by log2e/32
__device__ float g_kqv[SEQ * D3];
// V transposed per feature, j-permuted within 8-groups for PV fragments: g_vT[h*64+d][j']
__device__ float g_vT[DM * SEQ];

// ---------------------------------------------------------------------------
// helpers
// ---------------------------------------------------------------------------
static __device__ __forceinline__ unsigned s2u(const void* p) {
    return (unsigned)__cvta_generic_to_shared(p);
}
static __device__ __forceinline__ void ldsm4(unsigned* r, unsigned a) {
    asm volatile("ldmatrix.sync.aligned.m8n8.x4.shared.b16 {%0,%1,%2,%3}, [%4];"
                 : "=r"(r[0]), "=r"(r[1]), "=r"(r[2]), "=r"(r[3]) : "r"(a));
}
static __device__ __forceinline__ float tf32r(float x) {
    unsigned u; asm("cvt.rna.tf32.f32 %0, %1;" : "=r"(u) : "f"(x));
    return __uint_as_float(u);
}
static __device__ __forceinline__ void mma_tf32(float* c, const unsigned* a, const unsigned* b) {
    asm volatile("mma.sync.aligned.m16n8k8.row.col.f32.tf32.tf32.f32 "
                 "{%0,%1,%2,%3}, {%4,%5,%6,%7}, {%8,%9}, {%0,%1,%2,%3};"
                 : "+f"(c[0]), "+f"(c[1]), "+f"(c[2]), "+f"(c[3])
                 : "r"(a[0]), "r"(a[1]), "r"(a[2]), "r"(a[3]), "r"(b[0]), "r"(b[1]));
}
static __device__ __forceinline__ void ldA(unsigned* a, const float* base, int r0, int c0, int ld) {
    const int lane = threadIdx.x & 31;
    int row = r0 + (lane & 7) + ((lane >> 3) & 1) * 8;
    int col = c0 + (lane >> 4) * 4;
    ldsm4(a, s2u(base + row * ld + col));
}
static __device__ __forceinline__ void ldB(unsigned* b, const float* base, int n0, int c0, int ld) {
    const int lane = threadIdx.x & 31;
    int row = n0 + (lane & 7) + (lane >> 4) * 8;
    int col = c0 + ((lane >> 3) & 1) * 4;
    ldsm4(b, s2u(base + row * ld + col));
}
static __device__ __forceinline__ void cpa16(unsigned s, const void* g) {
    asm volatile("cp.async.cg.shared.global [%0], [%1], 16;" :: "r"(s), "l"(g) : "memory");
}
#define CP_COMMIT() asm volatile("cp.async.commit_group;" ::: "memory")
#define CP_WAIT(n)  asm volatile("cp.async.wait_group %0;" :: "n"(n) : "memory")

// ---------------------------------------------------------------------------
// Kernel 0: merged prep — blocks [0,4096): round x; [4096,7168): transpose+round W
// ---------------------------------------------------------------------------
__global__ __launch_bounds__(256) void prep(const float* __restrict__ x,
                                            const float* __restrict__ W) {
    if (blockIdx.x < 4096) {
        int i = blockIdx.x * 256 + threadIdx.x;
        float4 v = ((const float4*)x)[i];
        v.x = tf32r(v.x); v.y = tf32r(v.y); v.z = tf32r(v.z); v.w = tf32r(v.w);
        ((float4*)g_xr)[i] = v;
    } else {
        __shared__ float t[32][33];
        const int bid = blockIdx.x - 4096;             // 3072 blocks = 96 x 32
        const int n0 = (bid % 96) * 32, k0 = (bid / 96) * 32;
        const int xc = threadIdx.x & 31, y = threadIdx.x >> 5;   // 32 x 8
#pragma unroll
        for (int i = 0; i < 4; i++)
            t[y + i * 8][xc] = W[(size_t)(k0 + y + i * 8) * D3 + n0 + xc];
        __syncthreads();
#pragma unroll
        for (int i = 0; i < 4; i++) {
            int nn = y + i * 8;
            g_wt[(size_t)(n0 + nn) * DM + k0 + xc] = tf32r(t[xc][nn]);
        }
    }
}

// ---------------------------------------------------------------------------
// Kernel 1: kqv = x @ w (tf32 mma.sync). CTA 128x128, BK=32, 4 warps (64x64),
// double-buffered cp.async, one __syncthreads per K-chunk.
// Epilogue: K -> g_kqv; Q -> g_kqv scaled by log2e/32;
//           V -> g_vT transposed AND j-permuted (pi within 8-groups) via smem.
// ---------------------------------------------------------------------------
static __device__ __forceinline__ void gemm_stage_load(float* As, float* Bs,
                                                       int bm, int bn, int k0, int tid) {
#pragma unroll
    for (int p = 0; p < 8; p++) {
        int idx = tid + p * 128;
        int r = idx >> 3, c8 = idx & 7;
        cpa16(s2u(As + r * LG + c8 * 4), g_xr + (size_t)(bm + r) * DM + k0 + c8 * 4);
        cpa16(s2u(Bs + r * LG + c8 * 4), g_wt + (size_t)(bn + r) * DM + k0 + c8 * 4);
    }
}

__global__ __launch_bounds__(128) void gemm_kqv() {
    extern __shared__ __align__(16) float gsm[];
    const int tid = threadIdx.x, lane = tid & 31, wid = tid >> 5;
    const int bm = blockIdx.y * 128, bn = blockIdx.x * 128;
    const int wm = (wid >> 1) * 64, wn = (wid & 1) * 64;

    float c[4][8][4];
#pragma unroll
    for (int i = 0; i < 4; i++)
#pragma unroll
        for (int j = 0; j < 8; j++)
#pragma unroll
            for (int e = 0; e < 4; e++) c[i][j][e] = 0.f;

    gemm_stage_load(gsm, gsm + 4608, bm, bn, 0, tid);
    CP_COMMIT();

    for (int kc = 0; kc < 32; kc++) {
        CP_WAIT(0);
        __syncthreads();
        if (kc < 31) {
            float* base = gsm + ((kc + 1) & 1) * 9216;
            gemm_stage_load(base, base + 4608, bm, bn, (kc + 1) * 32, tid);
            CP_COMMIT();
        }
        const float* As = gsm + (kc & 1) * 9216;
        const float* Bs = As + 4608;
#pragma unroll
        for (int ks = 0; ks < 4; ks++) {
            unsigned af[4][4], bf[4][4];
#pragma unroll
            for (int mt = 0; mt < 4; mt++) ldA(af[mt], As, wm + mt * 16, ks * 8, LG);
#pragma unroll
            for (int np = 0; np < 4; np++) ldB(bf[np], Bs, wn + np * 16, ks * 8, LG);
#pragma unroll
            for (int mt = 0; mt < 4; mt++)
#pragma unroll
                for (int np = 0; np < 4; np++) {
                    mma_tf32(c[mt][np * 2],     af[mt], bf[np]);
                    mma_tf32(c[mt][np * 2 + 1], af[mt], bf[np] + 2);
                }
        }
    }

    if (bn < 2 * DM) {
        const float scl = (bn >= DM) ? 0.04508422f : 1.0f;   // log2(e)/32 for Q
#pragma unroll
        for (int mt = 0; mt < 4; mt++) {
            int r = bm + wm + mt * 16 + (lane >> 2);
#pragma unroll
            for (int nt = 0; nt < 8; nt++) {
                int col = bn + wn + nt * 8 + (lane & 3) * 2;
                *(float2*)&g_kqv[(size_t)r * D3 + col] =
                    make_float2(tf32r(c[mt][nt][0] * scl), tf32r(c[mt][nt][1] * scl));
                *(float2*)&g_kqv[(size_t)(r + 8) * D3 + col] =
                    make_float2(tf32r(c[mt][nt][2] * scl), tf32r(c[mt][nt][3] * scl));
            }
        }
    } else {
        // V chunk -> g_vT transposed, rows j permuted within 8-groups:
        // position p holds j with  j even -> p=j/2,  j odd -> p=4+(j-1)/2,
        // so PV can use S-accumulator fragments {c0,c2,c1,c3} directly as A.
        __syncthreads();
        float* T = gsm;      // 128 x 132 floats = 67584 B
        const int q = lane >> 2;                         // 0..7, j-within-group
        const int p = (q & 1) ? (4 + (q >> 1)) : (q >> 1);
#pragma unroll
        for (int mt = 0; mt < 4; mt++) {
            int g0 = wm + mt * 16;                       // 8-group base (q spans 0..7)
#pragma unroll
            for (int nt = 0; nt < 8; nt++) {
                int cc = wn + nt * 8 + (lane & 3) * 2;
                T[cc * 132 + g0 + p]           = c[mt][nt][0];
                T[(cc + 1) * 132 + g0 + p]     = c[mt][nt][1];
                T[cc * 132 + g0 + 8 + p]       = c[mt][nt][2];
                T[(cc + 1) * 132 + g0 + 8 + p] = c[mt][nt][3];
            }
        }
        __syncthreads();
#pragma unroll
        for (int pp = 0; pp < 32; pp++) {
            int i = tid + pp * 128;
            int cc = i >> 5, r4 = (i & 31) * 4;
            float4 v = *(float4*)&T[cc * 132 + r4];
            v.x = tf32r(v.x); v.y = tf32r(v.y); v.z = tf32r(v.z); v.w = tf32r(v.w);
            *(float4*)&g_vT[(size_t)(bn - 2 * DM + cc) * SEQ + bm + r4] = v;
        }
    }
}

// ---------------------------------------------------------------------------
// Kernel 2: flash attention — 4 warps x 32 rows, exp2-domain softmax,
// P kept in registers (permuted-V trick), double-buffered K/V, 1 barrier/tile.
// smem: QS[128][LA] | KS0|KS1|VT0|VT1 [64][LA] each = 104448 B (2 CTAs/SM)
// ---------------------------------------------------------------------------
static __device__ __forceinline__ void attn_tile_load(float* KS, float* VT,
                                                      int kv0, int h, int tid) {
#pragma unroll
    for (int p = 0; p < 8; p++) {
        int ch = tid + p * 128;
        int r = ch >> 4, c4 = (ch & 15) * 4;
        cpa16(s2u(&KS[r * LA + c4]), g_kqv + (size_t)(kv0 + r) * D3 + h * 64 + c4);
        cpa16(s2u(&VT[r * LA + c4]), g_vT + (size_t)(h * 64 + r) * SEQ + kv0 + c4);
    }
}

__global__ __launch_bounds__(128, 2) void attn_kernel(float* __restrict__ out) {
    extern __shared__ __align__(16) float sm[];
    float* QS  = sm;                       // Q (pre-scaled, tf32), persists
    float* KSb = sm + 128 * LA;            // KS0 | KS1
    float* VTb = sm + 256 * LA;            // VT0 | VT1

    const int tid = threadIdx.x, lane = tid & 31, wid = tid >> 5;
    const int h = blockIdx.y;
    const int qt = (int)gridDim.x - 1 - (int)blockIdx.x;   // heavy tiles first
    const int q0 = qt * 128;
    const int wr = wid * 32;
    const float slope = exp2f(-0.5f * (float)(h + 1)) * 1.44269504f;
    const int nt = 2 * qt + 2;

    // prologue: Q + K(0) + V(0), one group
#pragma unroll
    for (int p = 0; p < 16; p++) {
        int ch = tid + p * 128;
        int r = ch >> 4, c4 = (ch & 15) * 4;
        cpa16(s2u(&QS[r * LA + c4]), g_kqv + (size_t)(q0 + r) * D3 + DM + h * 64 + c4);
    }
    attn_tile_load(KSb, VTb, 0, h, tid);
    CP_COMMIT();

    float o0[8][4], o1[8][4];
#pragma unroll
    for (int ntl = 0; ntl < 8; ntl++)
#pragma unroll
        for (int e = 0; e < 4; e++) { o0[ntl][e] = 0.f; o1[ntl][e] = 0.f; }
    float m[4] = {-1e30f, -1e30f, -1e30f, -1e30f};
    float l[4] = {0.f, 0.f, 0.f, 0.f};

    // softmax of one 16-row m-tile; leaves s holding tf32-rounded P in place
    auto softmax_mt = [&](float (*s)[4], float (*o)[4], int mt, int kv0, bool domask)
        __attribute__((always_inline)) {
        const int gi0 = q0 + wr + mt * 16 + (lane >> 2);
        float ml0 = -1e30f, ml1 = -1e30f;
#pragma unroll
        for (int ntl = 0; ntl < 8; ntl++) {
#pragma unroll
            for (int e = 0; e < 2; e++) {
                int gj = kv0 + ntl * 8 + (lane & 3) * 2 + e;
                float v0 = fmaf(slope, (float)(gj - gi0), s[ntl][e]);
                if (domask && gj > gi0) v0 = -1e30f;
                s[ntl][e] = v0; ml0 = fmaxf(ml0, v0);
                float v1 = fmaf(slope, (float)(gj - (gi0 + 8)), s[ntl][2 + e]);
                if (domask && gj > gi0 + 8) v1 = -1e30f;
                s[ntl][2 + e] = v1; ml1 = fmaxf(ml1, v1);
            }
        }
        ml0 = fmaxf(ml0, __shfl_xor_sync(0xffffffffu, ml0, 1));
        ml0 = fmaxf(ml0, __shfl_xor_sync(0xffffffffu, ml0, 2));
        ml1 = fmaxf(ml1, __shfl_xor_sync(0xffffffffu, ml1, 1));
        ml1 = fmaxf(ml1, __shfl_xor_sync(0xffffffffu, ml1, 2));
        float mn0 = fmaxf(m[2 * mt], ml0), mn1 = fmaxf(m[2 * mt + 1], ml1);
        float a0 = exp2f(m[2 * mt] - mn0), a1 = exp2f(m[2 * mt + 1] - mn1);
        m[2 * mt] = mn0; m[2 * mt + 1] = mn1;
        float rs0 = 0.f, rs1 = 0.f;
#pragma unroll
        for (int ntl = 0; ntl < 8; ntl++) {
#pragma unroll
            for (int e = 0; e < 2; e++) {
                float p0 = exp2f(s[ntl][e] - mn0);     s[ntl][e] = p0;     rs0 += p0;
                float p1 = exp2f(s[ntl][2 + e] - mn1); s[ntl][2 + e] = p1; rs1 += p1;
            }
        }
        rs0 += __shfl_xor_sync(0xffffffffu, rs0, 1);
        rs0 += __shfl_xor_sync(0xffffffffu, rs0, 2);
        rs1 += __shfl_xor_sync(0xffffffffu, rs1, 1);
        rs1 += __shfl_xor_sync(0xffffffffu, rs1, 2);
        l[2 * mt]     = l[2 * mt] * a0 + rs0;
        l[2 * mt + 1] = l[2 * mt + 1] * a1 + rs1;
#pragma unroll
        for (int ntl = 0; ntl < 8; ntl++) {
            o[ntl][0] *= a0; o[ntl][1] *= a0; o[ntl][2] *= a1; o[ntl][3] *= a1;
        }
        // in-place tf32 round: s now IS the PV A-operand (no extra registers)
#pragma unroll
        for (int ntl = 0; ntl < 8; ntl++)
#pragma unroll
            for (int e = 0; e < 4; e++) s[ntl][e] = tf32r(s[ntl][e]);
    };

    for (int t = 0; t < nt; t++) {
        const int kv0 = t * 64;
        const int buf = t & 1;
        const bool active = (kv0 <= q0 + wr + 31);

        CP_WAIT(0);          // tile t (and Q on t==0) fully arrived
        __syncthreads();     // visible to all; all warps done with buf^1 (tile t-1)

        if (t + 1 < nt) {    // prefetch t+1 into the other buffer
            attn_tile_load(KSb + (buf ^ 1) * 64 * LA, VTb + (buf ^ 1) * 64 * LA,
                           (t + 1) * 64, h, tid);
            CP_COMMIT();
        }

        if (active) {
            const float* KS = KSb + buf * 64 * LA;
            const float* VT = VTb + buf * 64 * LA;

            // --- S = Q K^T ---
            float s0[8][4], s1[8][4];
#pragma unroll
            for (int ntl = 0; ntl < 8; ntl++)
#pragma unroll
                for (int e = 0; e < 4; e++) { s0[ntl][e] = 0.f; s1[ntl][e] = 0.f; }
#pragma unroll
            for (int ks = 0; ks < 8; ks++) {
                unsigned qf0[4], qf1[4];
                ldA(qf0, QS, wr,      ks * 8, LA);
                ldA(qf1, QS, wr + 16, ks * 8, LA);
#pragma unroll
                for (int np = 0; np < 4; np++) {
                    unsigned bf[4];
                    ldB(bf, KS, np * 16, ks * 8, LA);
                    mma_tf32(s0[np * 2],     qf0, bf);
                    mma_tf32(s0[np * 2 + 1], qf0, bf + 2);
                    mma_tf32(s1[np * 2],     qf1, bf);
                    mma_tf32(s1[np * 2 + 1], qf1, bf + 2);
                }
            }

            // --- softmax (exp2 domain), in-place tf32 round ---
            if (t >= nt - 2) {
                softmax_mt(s0, o0, 0, kv0, true);
                softmax_mt(s1, o1, 1, kv0, true);
            } else {
                softmax_mt(s0, o0, 0, kv0, false);
                softmax_mt(s1, o1, 1, kv0, false);
            }

            // --- O += P @ V: s registers aliased as A-fragments {c0,c2,c1,c3};
            //     V pre-permuted in g_vT, fragments shared across both m-tiles ---
#pragma unroll
            for (int ntl = 0; ntl < 8; ntl++) {
                unsigned a0f[4] = {__float_as_uint(s0[ntl][0]), __float_as_uint(s0[ntl][2]),
                                   __float_as_uint(s0[ntl][1]), __float_as_uint(s0[ntl][3])};
                unsigned a1f[4] = {__float_as_uint(s1[ntl][0]), __float_as_uint(s1[ntl][2]),
                                   __float_as_uint(s1[ntl][1]), __float_as_uint(s1[ntl][3])};
#pragma unroll
                for (int dp = 0; dp < 4; dp++) {
                    unsigned vf[4];
                    ldB(vf, VT, dp * 16, ntl * 8, LA);
                    mma_tf32(o0[dp * 2],     a0f, vf);
                    mma_tf32(o0[dp * 2 + 1], a0f, vf + 2);
                    mma_tf32(o1[dp * 2],     a1f, vf);
                    mma_tf32(o1[dp * 2 + 1], a1f, vf + 2);
                }
            }
        }
        // no end-of-loop barrier: next iteration's top barrier protects buffers
    }

    float rl[4] = {1.f / l[0], 1.f / l[1], 1.f / l[2], 1.f / l[3]};
#pragma unroll
    for (int mt = 0; mt < 2; mt++) {
        float (*o)[4] = mt ? o1 : o0;
        const int r = q0 + wr + mt * 16 + (lane >> 2);
#pragma unroll
        for (int ntl = 0; ntl < 8; ntl++) {
            int col = h * 64 + ntl * 8 + (lane & 3) * 2;
            *(float2*)&out[(size_t)r * DM + col] =
                make_float2(o[ntl][0] * rl[2 * mt], o[ntl][1] * rl[2 * mt]);
            *(float2*)&out[(size_t)(r + 8) * DM + col] =
                make_float2(o[ntl][2] * rl[2 * mt + 1], o[ntl][3] * rl[2 * mt + 1]);
        }
    }
}

// ---------------------------------------------------------------------------
// Launch
// ---------------------------------------------------------------------------
extern "C" void kernel_launch(void* const* d_in, const int* in_sizes, int n_in,
                              void* d_out, int out_size) {
    const float* x = (const float*)d_in[0];   // [1, 4096, 1024]
    const float* w = (const float*)d_in[1];   // [1024, 3072]
    float* out = (float*)d_out;

    const int gemm_smem = 2 * 2 * 128 * LG * (int)sizeof(float);   // 73728 B
    cudaFuncSetAttribute(gemm_kqv, cudaFuncAttributeMaxDynamicSharedMemorySize, gemm_smem);
    const int attn_smem = 384 * LA * (int)sizeof(float);           // 104448 B
    cudaFuncSetAttribute(attn_kernel, cudaFuncAttributeMaxDynamicSharedMemorySize, attn_smem);

    prep<<<4096 + 3072, 256>>>(x, w);
    gemm_kqv<<<dim3(D3 / 128, SEQ / 128), 128, gemm_smem>>>();
    attn_kernel<<<dim3(SEQ / 128, NH), 128, attn_smem>>>(out);
}

// round 17
// speedup vs baseline: 1.4394x; 1.4394x over previous
#include <cuda_runtime.h>

#define SEQ 4096
#define DM  1024
#define NH  16
#define D3  3072
#define LA  68     // attn smem row stride (floats)
#define LG  36     // gemm smem row stride (floats)

// tf32-rounded operands for the projection GEMM
__device__ float g_xr[SEQ * DM];    // x, rounded
__device__ float g_wt[D3 * DM];     // W^T [n][k], rounded
// fp32 scratch: kqv K|Q chunks (V chunk unused), tf32-rounded, Q pre-scaled by log2e/32
__device__ float g_kqv[SEQ * D3];
// V transposed per feature: g_vT[h*64+d][j]  (written directly by gemm epilogue)
__device__ float g_vT[DM * SEQ];

// ---------------------------------------------------------------------------
// helpers
// ---------------------------------------------------------------------------
static __device__ __forceinline__ unsigned s2u(const void* p) {
    return (unsigned)__cvta_generic_to_shared(p);
}
static __device__ __forceinline__ void ldsm4(unsigned* r, unsigned a) {
    asm volatile("ldmatrix.sync.aligned.m8n8.x4.shared.b16 {%0,%1,%2,%3}, [%4];"
                 : "=r"(r[0]), "=r"(r[1]), "=r"(r[2]), "=r"(r[3]) : "r"(a));
}
static __device__ __forceinline__ float tf32r(float x) {
    unsigned u; asm("cvt.rna.tf32.f32 %0, %1;" : "=r"(u) : "f"(x));
    return __uint_as_float(u);
}
static __device__ __forceinline__ void mma_tf32(float* c, const unsigned* a, const unsigned* b) {
    asm volatile("mma.sync.aligned.m16n8k8.row.col.f32.tf32.tf32.f32 "
                 "{%0,%1,%2,%3}, {%4,%5,%6,%7}, {%8,%9}, {%0,%1,%2,%3};"
                 : "+f"(c[0]), "+f"(c[1]), "+f"(c[2]), "+f"(c[3])
                 : "r"(a[0]), "r"(a[1]), "r"(a[2]), "r"(a[3]), "r"(b[0]), "r"(b[1]));
}
static __device__ __forceinline__ void ldA(unsigned* a, const float* base, int r0, int c0, int ld) {
    const int lane = threadIdx.x & 31;
    int row = r0 + (lane & 7) + ((lane >> 3) & 1) * 8;
    int col = c0 + (lane >> 4) * 4;
    ldsm4(a, s2u(base + row * ld + col));
}
static __device__ __forceinline__ void ldB(unsigned* b, const float* base, int n0, int c0, int ld) {
    const int lane = threadIdx.x & 31;
    int row = n0 + (lane & 7) + (lane >> 4) * 8;
    int col = c0 + ((lane >> 3) & 1) * 4;
    ldsm4(b, s2u(base + row * ld + col));
}
static __device__ __forceinline__ void cpa16(unsigned s, const void* g) {
    asm volatile("cp.async.cg.shared.global [%0], [%1], 16;" :: "r"(s), "l"(g) : "memory");
}
#define CP_COMMIT() asm volatile("cp.async.commit_group;" ::: "memory")
#define CP_WAIT(n)  asm volatile("cp.async.wait_group %0;" :: "n"(n) : "memory")

// ---------------------------------------------------------------------------
// Kernel 0: merged prep — blocks [0,4096): round x; [4096,7168): transpose+round W
// ---------------------------------------------------------------------------
__global__ __launch_bounds__(256) void prep(const float* __restrict__ x,
                                            const float* __restrict__ W) {
    if (blockIdx.x < 4096) {
        int i = blockIdx.x * 256 + threadIdx.x;        // SEQ*DM/4 = 1048576 float4s
        float4 v = ((const float4*)x)[i];
        v.x = tf32r(v.x); v.y = tf32r(v.y); v.z = tf32r(v.z); v.w = tf32r(v.w);
        ((float4*)g_xr)[i] = v;
    } else {
        __shared__ float t[32][33];
        const int bid = blockIdx.x - 4096;             // 3072 blocks = 96 x 32
        const int n0 = (bid % 96) * 32, k0 = (bid / 96) * 32;
        const int xc = threadIdx.x & 31, y = threadIdx.x >> 5;   // 32 x 8
#pragma unroll
        for (int i = 0; i < 4; i++)
            t[y + i * 8][xc] = W[(size_t)(k0 + y + i * 8) * D3 + n0 + xc];
        __syncthreads();
#pragma unroll
        for (int i = 0; i < 4; i++) {
            int nn = y + i * 8;
            g_wt[(size_t)(n0 + nn) * DM + k0 + xc] = tf32r(t[xc][nn]);
        }
    }
}

// ---------------------------------------------------------------------------
// Kernel 1: kqv = x @ w (tf32 mma.sync). CTA 128x128, BK=32, 4 warps (64x64 tiles),
// double-buffered cp.async, ONE __syncthreads per K-chunk.
// Epilogue: K chunk -> g_kqv; Q chunk -> g_kqv scaled by log2e/32;
//           V chunk -> g_vT TRANSPOSED via smem staging (g_kqv V never written).
// ---------------------------------------------------------------------------
static __device__ __forceinline__ void gemm_stage_load(float* As, float* Bs,
                                                       int bm, int bn, int k0, int tid) {
#pragma unroll
    for (int p = 0; p < 8; p++) {
        int idx = tid + p * 128;
        int r = idx >> 3, c8 = idx & 7;
        cpa16(s2u(As + r * LG + c8 * 4), g_xr + (size_t)(bm + r) * DM + k0 + c8 * 4);
        cpa16(s2u(Bs + r * LG + c8 * 4), g_wt + (size_t)(bn + r) * DM + k0 + c8 * 4);
    }
}

__global__ __launch_bounds__(128) void gemm_kqv() {
    extern __shared__ __align__(16) float gsm[];
    const int tid = threadIdx.x, lane = tid & 31, wid = tid >> 5;
    const int bm = blockIdx.y * 128, bn = blockIdx.x * 128;
    const int wm = (wid >> 1) * 64, wn = (wid & 1) * 64;

    float c[4][8][4];
#pragma unroll
    for (int i = 0; i < 4; i++)
#pragma unroll
        for (int j = 0; j < 8; j++)
#pragma unroll
            for (int e = 0; e < 4; e++) c[i][j][e] = 0.f;

    gemm_stage_load(gsm, gsm + 4608, bm, bn, 0, tid);
    CP_COMMIT();

    for (int kc = 0; kc < 32; kc++) {
        CP_WAIT(0);          // chunk kc resident
        __syncthreads();     // visible to all; also proves compute(kc-1) done => other buf free
        if (kc < 31) {
            float* base = gsm + ((kc + 1) & 1) * 9216;
            gemm_stage_load(base, base + 4608, bm, bn, (kc + 1) * 32, tid);
            CP_COMMIT();
        }
        const float* As = gsm + (kc & 1) * 9216;
        const float* Bs = As + 4608;
#pragma unroll
        for (int ks = 0; ks < 4; ks++) {
            unsigned af[4][4], bf[4][4];
#pragma unroll
            for (int mt = 0; mt < 4; mt++) ldA(af[mt], As, wm + mt * 16, ks * 8, LG);
#pragma unroll
            for (int np = 0; np < 4; np++) ldB(bf[np], Bs, wn + np * 16, ks * 8, LG);
#pragma unroll
            for (int mt = 0; mt < 4; mt++)
#pragma unroll
                for (int np = 0; np < 4; np++) {
                    mma_tf32(c[mt][np * 2],     af[mt], bf[np]);
                    mma_tf32(c[mt][np * 2 + 1], af[mt], bf[np] + 2);
                }
        }
    }

    if (bn < 2 * DM) {
        // K / Q chunks -> g_kqv.  Q pre-scale: log2(e)/sqrt(D) = 1.44269504/32
        const float scl = (bn >= DM) ? 0.04508422f : 1.0f;
#pragma unroll
        for (int mt = 0; mt < 4; mt++) {
            int r = bm + wm + mt * 16 + (lane >> 2);
#pragma unroll
            for (int nt = 0; nt < 8; nt++) {
                int col = bn + wn + nt * 8 + (lane & 3) * 2;
                *(float2*)&g_kqv[(size_t)r * D3 + col] =
                    make_float2(tf32r(c[mt][nt][0] * scl), tf32r(c[mt][nt][1] * scl));
                *(float2*)&g_kqv[(size_t)(r + 8) * D3 + col] =
                    make_float2(tf32r(c[mt][nt][2] * scl), tf32r(c[mt][nt][3] * scl));
            }
        }
    } else {
        // V chunk -> g_vT transposed. Stage T[col][row] in smem (stride 132,
        // store bank = 8j+q -> conflict-free), then coalesced float4 writes.
        __syncthreads();     // mainloop smem reads complete in all warps
        float* T = gsm;      // 128 x 132 floats = 67584 B <= 73728 B
#pragma unroll
        for (int mt = 0; mt < 4; mt++) {
            int rr = wm + mt * 16 + (lane >> 2);
#pragma unroll
            for (int nt = 0; nt < 8; nt++) {
                int cc = wn + nt * 8 + (lane & 3) * 2;
                T[cc * 132 + rr]           = c[mt][nt][0];
                T[(cc + 1) * 132 + rr]     = c[mt][nt][1];
                T[cc * 132 + rr + 8]       = c[mt][nt][2];
                T[(cc + 1) * 132 + rr + 8] = c[mt][nt][3];
            }
        }
        __syncthreads();
#pragma unroll
        for (int p = 0; p < 32; p++) {
            int i = tid + p * 128;
            int cc = i >> 5, r4 = (i & 31) * 4;
            float4 v = *(float4*)&T[cc * 132 + r4];
            v.x = tf32r(v.x); v.y = tf32r(v.y); v.z = tf32r(v.z); v.w = tf32r(v.w);
            *(float4*)&g_vT[(size_t)(bn - 2 * DM + cc) * SEQ + bm + r4] = v;
        }
    }
}

// ---------------------------------------------------------------------------
// Kernel 2: flash attention — the 493.6us configuration (PS staging, 4 warps x
// 32 rows, exp2-domain softmax, masked/unmasked split, eager single-buffer
// cp.async pipeline). Only change: final-tile K-prefetch load elided.
// smem: QS[128][LA] | PS[128][LA] | KS[64][LA] | VT[64][LA] = 104448 B (2 CTAs/SM)
// ---------------------------------------------------------------------------
__global__ __launch_bounds__(128, 2) void attn_kernel(float* __restrict__ out) {
    extern __shared__ __align__(16) float sm[];
    float* QS = sm;
    float* PS = sm + 128 * LA;
    float* KS = sm + 256 * LA;
    float* VT = sm + 320 * LA;

    const int tid = threadIdx.x, lane = tid & 31, wid = tid >> 5;
    const int h = blockIdx.y;
    const int qt = (int)gridDim.x - 1 - (int)blockIdx.x;
    const int q0 = qt * 128;
    const int wr = wid * 32;
    const float slope = exp2f(-0.5f * (float)(h + 1)) * 1.44269504f;
    const int nt = 2 * qt + 2;

#pragma unroll
    for (int p = 0; p < 16; p++) {
        int ch = tid + p * 128;
        int r = ch >> 4, c4 = (ch & 15) * 4;
        cpa16(s2u(&QS[r * LA + c4]), g_kqv + (size_t)(q0 + r) * D3 + DM + h * 64 + c4);
    }
#pragma unroll
    for (int p = 0; p < 8; p++) {
        int ch = tid + p * 128;
        int r = ch >> 4, c4 = (ch & 15) * 4;
        cpa16(s2u(&KS[r * LA + c4]), g_kqv + (size_t)r * D3 + h * 64 + c4);
    }
    CP_COMMIT();

    float o0[8][4], o1[8][4];
#pragma unroll
    for (int ntl = 0; ntl < 8; ntl++)
#pragma unroll
        for (int e = 0; e < 4; e++) { o0[ntl][e] = 0.f; o1[ntl][e] = 0.f; }
    float m[4] = {-1e30f, -1e30f, -1e30f, -1e30f};
    float l[4] = {0.f, 0.f, 0.f, 0.f};

    auto softmax_mt = [&](float (*s)[4], float (*o)[4], int mt, int kv0, bool domask)
        __attribute__((always_inline)) {
        const int gi0 = q0 + wr + mt * 16 + (lane >> 2);
        float ml0 = -1e30f, ml1 = -1e30f;
#pragma unroll
        for (int ntl = 0; ntl < 8; ntl++) {
#pragma unroll
            for (int e = 0; e < 2; e++) {
                int gj = kv0 + ntl * 8 + (lane & 3) * 2 + e;
                float v0 = fmaf(slope, (float)(gj - gi0), s[ntl][e]);
                if (domask && gj > gi0) v0 = -1e30f;
                s[ntl][e] = v0; ml0 = fmaxf(ml0, v0);
                float v1 = fmaf(slope, (float)(gj - (gi0 + 8)), s[ntl][2 + e]);
                if (domask && gj > gi0 + 8) v1 = -1e30f;
                s[ntl][2 + e] = v1; ml1 = fmaxf(ml1, v1);
            }
        }
        ml0 = fmaxf(ml0, __shfl_xor_sync(0xffffffffu, ml0, 1));
        ml0 = fmaxf(ml0, __shfl_xor_sync(0xffffffffu, ml0, 2));
        ml1 = fmaxf(ml1, __shfl_xor_sync(0xffffffffu, ml1, 1));
        ml1 = fmaxf(ml1, __shfl_xor_sync(0xffffffffu, ml1, 2));
        float mn0 = fmaxf(m[2 * mt], ml0), mn1 = fmaxf(m[2 * mt + 1], ml1);
        float a0 = exp2f(m[2 * mt] - mn0), a1 = exp2f(m[2 * mt + 1] - mn1);
        m[2 * mt] = mn0; m[2 * mt + 1] = mn1;
        float rs0 = 0.f, rs1 = 0.f;
#pragma unroll
        for (int ntl = 0; ntl < 8; ntl++) {
#pragma unroll
            for (int e = 0; e < 2; e++) {
                float p0 = exp2f(s[ntl][e] - mn0);     s[ntl][e] = p0;     rs0 += p0;
                float p1 = exp2f(s[ntl][2 + e] - mn1); s[ntl][2 + e] = p1; rs1 += p1;
            }
        }
        rs0 += __shfl_xor_sync(0xffffffffu, rs0, 1);
        rs0 += __shfl_xor_sync(0xffffffffu, rs0, 2);
        rs1 += __shfl_xor_sync(0xffffffffu, rs1, 1);
        rs1 += __shfl_xor_sync(0xffffffffu, rs1, 2);
        l[2 * mt]     = l[2 * mt] * a0 + rs0;
        l[2 * mt + 1] = l[2 * mt + 1] * a1 + rs1;
#pragma unroll
        for (int ntl = 0; ntl < 8; ntl++) {
            o[ntl][0] *= a0; o[ntl][1] *= a0; o[ntl][2] *= a1; o[ntl][3] *= a1;
        }
        const int pr = wr + mt * 16 + (lane >> 2);
        const int pc = (lane & 3) * 2;
#pragma unroll
        for (int ntl = 0; ntl < 8; ntl++) {
            *(float2*)&PS[pr * LA + ntl * 8 + pc] =
                make_float2(tf32r(s[ntl][0]), tf32r(s[ntl][1]));
            *(float2*)&PS[(pr + 8) * LA + ntl * 8 + pc] =
                make_float2(tf32r(s[ntl][2]), tf32r(s[ntl][3]));
        }
    };

    for (int t = 0; t < nt; t++) {
        const int kv0 = t * 64;
        const bool active = (kv0 <= q0 + wr + 31);

#pragma unroll
        for (int p = 0; p < 8; p++) {
            int ch = tid + p * 128;
            int d = ch >> 4, j4 = (ch & 15) * 4;
            cpa16(s2u(&VT[d * LA + j4]), g_vT + (size_t)(h * 64 + d) * SEQ + kv0 + j4);
        }
        CP_COMMIT();

        CP_WAIT(1);
        __syncthreads();

        float s0[8][4], s1[8][4];
        if (active) {
#pragma unroll
            for (int ntl = 0; ntl < 8; ntl++)
#pragma unroll
                for (int e = 0; e < 4; e++) { s0[ntl][e] = 0.f; s1[ntl][e] = 0.f; }
#pragma unroll
            for (int ks = 0; ks < 8; ks++) {
                unsigned qf0[4], qf1[4];
                ldA(qf0, QS, wr,      ks * 8, LA);
                ldA(qf1, QS, wr + 16, ks * 8, LA);
#pragma unroll
                for (int np = 0; np < 4; np++) {
                    unsigned bf[4];
                    ldB(bf, KS, np * 16, ks * 8, LA);
                    mma_tf32(s0[np * 2],     qf0, bf);
                    mma_tf32(s0[np * 2 + 1], qf0, bf + 2);
                    mma_tf32(s1[np * 2],     qf1, bf);
                    mma_tf32(s1[np * 2 + 1], qf1, bf + 2);
                }
            }
        }
        __syncthreads();

        {
            // prefetch K(t+1); load elided on the final tile (commit kept for ledger)
            if (t + 1 < nt) {
                const int kvn = (t + 1) * 64;
#pragma unroll
                for (int p = 0; p < 8; p++) {
                    int ch = tid + p * 128;
                    int r = ch >> 4, c4 = (ch & 15) * 4;
                    cpa16(s2u(&KS[r * LA + c4]), g_kqv + (size_t)(kvn + r) * D3 + h * 64 + c4);
                }
            }
            CP_COMMIT();
        }

        if (active) {
            if (t >= nt - 2) {
                softmax_mt(s0, o0, 0, kv0, true);
                softmax_mt(s1, o1, 1, kv0, true);
            } else {
                softmax_mt(s0, o0, 0, kv0, false);
                softmax_mt(s1, o1, 1, kv0, false);
            }
            __syncwarp();
        }

        CP_WAIT(1);
        __syncthreads();

        if (active) {
#pragma unroll
            for (int jk = 0; jk < 8; jk++) {
                unsigned pf0[4], pf1[4];
                ldA(pf0, PS, wr,      jk * 8, LA);
                ldA(pf1, PS, wr + 16, jk * 8, LA);
#pragma unroll
                for (int dp = 0; dp < 4; dp++) {
                    unsigned vf[4];
                    ldB(vf, VT, dp * 16, jk * 8, LA);
                    mma_tf32(o0[dp * 2],     pf0, vf);
                    mma_tf32(o0[dp * 2 + 1], pf0, vf + 2);
                    mma_tf32(o1[dp * 2],     pf1, vf);
                    mma_tf32(o1[dp * 2 + 1], pf1, vf + 2);
                }
            }
        }
        __syncthreads();
    }

    float rl[4] = {1.f / l[0], 1.f / l[1], 1.f / l[2], 1.f / l[3]};
#pragma unroll
    for (int mt = 0; mt < 2; mt++) {
        float (*o)[4] = mt ? o1 : o0;
        const int r = q0 + wr + mt * 16 + (lane >> 2);
#pragma unroll
        for (int ntl = 0; ntl < 8; ntl++) {
            int col = h * 64 + ntl * 8 + (lane & 3) * 2;
            *(float2*)&out[(size_t)r * DM + col] =
                make_float2(o[ntl][0] * rl[2 * mt], o[ntl][1] * rl[2 * mt]);
            *(float2*)&out[(size_t)(r + 8) * DM + col] =
                make_float2(o[ntl][2] * rl[2 * mt + 1], o[ntl][3] * rl[2 * mt + 1]);
        }
    }
}

// ---------------------------------------------------------------------------
// Launch
// ---------------------------------------------------------------------------
extern "C" void kernel_launch(void* const* d_in, const int* in_sizes, int n_in,
                              void* d_out, int out_size) {
    const float* x = (const float*)d_in[0];   // [1, 4096, 1024]
    const float* w = (const float*)d_in[1];   // [1024, 3072]
    float* out = (float*)d_out;

    const int gemm_smem = 2 * 2 * 128 * LG * (int)sizeof(float);   // 73728 B
    cudaFuncSetAttribute(gemm_kqv, cudaFuncAttributeMaxDynamicSharedMemorySize, gemm_smem);
    const int attn_smem = 384 * LA * (int)sizeof(float);           // 104448 B
    cudaFuncSetAttribute(attn_kernel, cudaFuncAttributeMaxDynamicSharedMemorySize, attn_smem);

    prep<<<4096 + 3072, 256>>>(x, w);
    gemm_kqv<<<dim3(D3 / 128, SEQ / 128), 128, gemm_smem>>>();
    attn_kernel<<<dim3(SEQ / 128, NH), 128, attn_smem>>>(out);
}